// round 2
// baseline (speedup 1.0000x reference)
#include <cuda_runtime.h>
#include <cstdint>
#include <cstddef>

// ---------------------------------------------------------------------------
// Problem dims (fixed): out[8192,4096] = x[8192,4096] @ W^T[4096,4096] + b
// W = mu + exp(log_sigma) * eps  (sampled once per call by prep kernel)
// ---------------------------------------------------------------------------
#define NROWS 8192
#define KDIM  4096
#define ODIM  4096

#define TILE_M 128
#define TILE_N 128
#define TILE_K 32
#define STAGES 3
#define K_ITERS (KDIM / TILE_K)            // 128

#define A_BYTES (TILE_M * TILE_K * 4)      // 16384
#define B_BYTES (TILE_N * TILE_K * 4)      // 16384
#define STAGE_BYTES (A_BYTES + B_BYTES)    // 32768
#define SMEM_TOTAL  (STAGES * STAGE_BYTES) // 98304

// ---------------------------------------------------------------------------
// Scratch (__device__ globals: the sanctioned allocation-free workaround)
// ---------------------------------------------------------------------------
__device__ float g_W[(size_t)ODIM * KDIM];  // tf32-rounded sampled weight [O][K]
__device__ float g_B[ODIM];                 // sampled bias (fp32)

// ---------------------------------------------------------------------------
// Helpers (baseline sm_103 ISA only: cp.async / mma.sync / cvt.rna.tf32)
// ---------------------------------------------------------------------------
__device__ __forceinline__ uint32_t smem_u32(const void* p) {
    uint32_t a;
    asm("{ .reg .u64 t; cvta.to.shared.u64 t, %1; cvt.u32.u64 %0, t; }"
        : "=r"(a) : "l"(p));
    return a;
}

__device__ __forceinline__ void cp16(uint32_t smem_dst, const void* gptr) {
    asm volatile("cp.async.cg.shared.global [%0], [%1], 16;"
                 :: "r"(smem_dst), "l"(gptr) : "memory");
}
#define CP_COMMIT() asm volatile("cp.async.commit_group;" ::: "memory")
#define CP_WAIT1()  asm volatile("cp.async.wait_group 1;" ::: "memory")

__device__ __forceinline__ uint32_t f2tf32(float x) {
    uint32_t o;
    asm("cvt.rna.tf32.f32 %0, %1;" : "=r"(o) : "f"(x));
    return o;
}

// Swizzled shared loads: addr = base + row*128 + ((col ^ ((row&7)<<2)) * 4)
__device__ __forceinline__ float lds_f32(uint32_t base, int row, int col) {
    uint32_t ad = base + (uint32_t)row * 128u +
                  (uint32_t)(((col ^ ((row & 7) << 2)) & 31) << 2);
    float v;
    asm volatile("ld.shared.f32 %0, [%1];" : "=f"(v) : "r"(ad));
    return v;
}
__device__ __forceinline__ uint32_t lds_u32(uint32_t base, int row, int col) {
    uint32_t ad = base + (uint32_t)row * 128u +
                  (uint32_t)(((col ^ ((row & 7) << 2)) & 31) << 2);
    uint32_t v;
    asm volatile("ld.shared.b32 %0, [%1];" : "=r"(v) : "r"(ad));
    return v;
}

__device__ __forceinline__ void mma_tf32(float* c, const uint32_t* a,
                                         const uint32_t* b) {
    asm volatile(
        "mma.sync.aligned.m16n8k8.row.col.f32.tf32.tf32.f32 "
        "{%0,%1,%2,%3}, {%4,%5,%6,%7}, {%8,%9}, {%0,%1,%2,%3};"
        : "+f"(c[0]), "+f"(c[1]), "+f"(c[2]), "+f"(c[3])
        : "r"(a[0]), "r"(a[1]), "r"(a[2]), "r"(a[3]), "r"(b[0]), "r"(b[1]));
}

// ---------------------------------------------------------------------------
// Prep kernels: sample W (tf32-rounded) and bias
// ---------------------------------------------------------------------------
__global__ void prep_w_kernel(const float4* __restrict__ mu,
                              const float4* __restrict__ ls,
                              const float4* __restrict__ eps) {
    size_t i = (size_t)blockIdx.x * blockDim.x + threadIdx.x;
    float4 m = mu[i], l = ls[i], e = eps[i];
    float4 o;
    o.x = __uint_as_float(f2tf32(m.x + expf(l.x) * e.x));
    o.y = __uint_as_float(f2tf32(m.y + expf(l.y) * e.y));
    o.z = __uint_as_float(f2tf32(m.z + expf(l.z) * e.z));
    o.w = __uint_as_float(f2tf32(m.w + expf(l.w) * e.w));
    reinterpret_cast<float4*>(g_W)[i] = o;
}

__global__ void prep_bias_kernel(const float* __restrict__ mub,
                                 const float* __restrict__ lsb,
                                 const float* __restrict__ epsb) {
    int i = blockIdx.x * blockDim.x + threadIdx.x;
    if (i < ODIM) g_B[i] = mub[i] + expf(lsb[i]) * epsb[i];
}

// ---------------------------------------------------------------------------
// GEMM kernel: 2048 CTAs (64 m-tiles x 32 n-tiles, n fastest), 256 threads.
// 8 warps in 2x4 layout; each warp owns a 64x32 output tile.
// ---------------------------------------------------------------------------
struct Producer {
    const float* gA;
    const float* gB;
    uint32_t swoff;
    uint32_t sb;
};

__device__ __forceinline__ void load_stage(const Producer& p, int slot, int kit) {
    uint32_t aB = p.sb + slot * STAGE_BYTES;
    uint32_t bB = aB + A_BYTES;
    const float* ga = p.gA + kit * TILE_K;
    const float* gb = p.gB + kit * TILE_K;
    #pragma unroll
    for (int i = 0; i < 4; ++i)
        cp16(aB + p.swoff + i * 32 * 128, ga + (size_t)i * 32 * KDIM);
    #pragma unroll
    for (int i = 0; i < 4; ++i)
        cp16(bB + p.swoff + i * 32 * 128, gb + (size_t)i * 32 * KDIM);
}

__global__ void __launch_bounds__(256, 2)
rand_linear_gemm_kernel(const float* __restrict__ X, float* __restrict__ out) {
    extern __shared__ char smem[];
    const uint32_t sb = smem_u32(smem);
    const int tid = threadIdx.x;
    const int lane = tid & 31;
    const int wid = tid >> 5;

    const int m_tile = blockIdx.x >> 5;    // 64
    const int n_tile = blockIdx.x & 31;    // 32 (fast-varying: W stays L2-hot)
    const int m0 = m_tile * TILE_M;
    const int n0 = n_tile * TILE_N;
    const int wm0 = (wid & 1) * 64;        // warp m offset in tile
    const int wn0 = (wid >> 1) * 32;       // warp n offset in tile

    // ---- producer setup: 256 threads fill both A(128x32) and B(128x32) ----
    const int tr = tid >> 3;               // 0..31 row group
    const int tc = tid & 7;                // 16B chunk within 128B row
    Producer p;
    p.gA = X + (size_t)(m0 + tr) * KDIM + tc * 4;
    p.gB = g_W + (size_t)(n0 + tr) * KDIM + tc * 4;
    p.swoff = (uint32_t)tr * 128u + (uint32_t)((tc ^ (tr & 7)) << 4);
    p.sb = sb;

    float acc[4][4][4];
    #pragma unroll
    for (int i = 0; i < 4; ++i)
        #pragma unroll
        for (int j = 0; j < 4; ++j)
            #pragma unroll
            for (int r = 0; r < 4; ++r) acc[i][j][r] = 0.f;

    // ---- prologue: fill 2 stages ----
    load_stage(p, 0, 0); CP_COMMIT();
    load_stage(p, 1, 1); CP_COMMIT();

    const int gid = lane >> 2;             // group id 0..7
    const int kc  = lane & 3;              // k sub-col 0..3

    // ---- main loop ----
    for (int it = 0; it < K_ITERS; ++it) {
        CP_WAIT1();
        __syncthreads();

        const int pf = it + 2;
        if (pf < K_ITERS) load_stage(p, pf % STAGES, pf);
        CP_COMMIT();

        const int slot = it % STAGES;
        const uint32_t aB = sb + slot * STAGE_BYTES;
        const uint32_t bB = aB + A_BYTES;

        #pragma unroll
        for (int kk = 0; kk < 4; ++kk) {
            const int c0 = kk * 8 + kc;
            const int c1 = c0 + 4;
            uint32_t a[4][4];
            #pragma unroll
            for (int i = 0; i < 4; ++i) {
                const int r0 = wm0 + i * 16 + gid;
                const int r1 = r0 + 8;
                a[i][0] = f2tf32(lds_f32(aB, r0, c0));
                a[i][1] = f2tf32(lds_f32(aB, r1, c0));
                a[i][2] = f2tf32(lds_f32(aB, r0, c1));
                a[i][3] = f2tf32(lds_f32(aB, r1, c1));
            }
            uint32_t b[4][2];
            #pragma unroll
            for (int j = 0; j < 4; ++j) {
                const int nr = wn0 + j * 8 + gid;   // W already tf32-rounded
                b[j][0] = lds_u32(bB, nr, c0);
                b[j][1] = lds_u32(bB, nr, c1);
            }
            #pragma unroll
            for (int i = 0; i < 4; ++i)
                #pragma unroll
                for (int j = 0; j < 4; ++j)
                    mma_tf32(acc[i][j], a[i], b[j]);
        }
    }

    // ---- epilogue: fused bias, float2 stores ----
    #pragma unroll
    for (int j = 0; j < 4; ++j) {
        const int col = n0 + wn0 + j * 8 + kc * 2;
        float2 bv;
        bv.x = __ldg(&g_B[col]);
        bv.y = __ldg(&g_B[col + 1]);
        #pragma unroll
        for (int i = 0; i < 4; ++i) {
            const int row = m0 + wm0 + i * 16 + gid;
            float2 v0 = make_float2(acc[i][j][0] + bv.x, acc[i][j][1] + bv.y);
            float2 v1 = make_float2(acc[i][j][2] + bv.x, acc[i][j][3] + bv.y);
            *reinterpret_cast<float2*>(out + (size_t)row * ODIM + col) = v0;
            *reinterpret_cast<float2*>(out + (size_t)(row + 8) * ODIM + col) = v1;
        }
    }
}

// ---------------------------------------------------------------------------
// Launch
// ---------------------------------------------------------------------------
extern "C" void kernel_launch(void* const* d_in, const int* in_sizes, int n_in,
                              void* d_out, int out_size) {
    const float* x    = (const float*)d_in[0];
    const float* muw  = (const float*)d_in[1];
    const float* lsw  = (const float*)d_in[2];
    const float* mub  = (const float*)d_in[3];
    const float* lsb  = (const float*)d_in[4];
    const float* epsw = (const float*)d_in[5];
    const float* epsb = (const float*)d_in[6];
    float* out = (float*)d_out;

    cudaFuncSetAttribute(rand_linear_gemm_kernel,
                         cudaFuncAttributeMaxDynamicSharedMemorySize, SMEM_TOTAL);

    // W: 4096*4096/4 = 4194304 float4 -> 16384 blocks of 256
    prep_w_kernel<<<16384, 256>>>((const float4*)muw, (const float4*)lsw,
                                  (const float4*)epsw);
    prep_bias_kernel<<<16, 256>>>(mub, lsb, epsb);

    rand_linear_gemm_kernel<<<(NROWS / TILE_M) * (ODIM / TILE_N), 256,
                              SMEM_TOTAL>>>(x, out);
}

// round 3
// speedup vs baseline: 1.0496x; 1.0496x over previous
#include <cuda_runtime.h>
#include <cstdint>
#include <cstddef>

// ---------------------------------------------------------------------------
// out[8192,4096] = x[8192,4096] @ W^T + b,  W = mu + exp(log_sigma)*eps
// Path: tf32 mma.sync (tcgen05 unavailable: harness PTX target = compute_103)
// ---------------------------------------------------------------------------
#define NROWS 8192
#define KDIM  4096
#define ODIM  4096

#define TILE_M 128
#define TILE_N 128
#define TILE_K 32
#define STAGES 3
#define K_ITERS (KDIM / TILE_K)            // 128

#define A_BYTES (TILE_M * TILE_K * 4)      // 16384
#define B_BYTES (TILE_N * TILE_K * 4)      // 16384
#define STAGE_BYTES (A_BYTES + B_BYTES)    // 32768
#define SMEM_TOTAL  (STAGES * STAGE_BYTES) // 98304

// ---------------------------------------------------------------------------
// Scratch (__device__ globals: sanctioned allocation-free workaround)
// ---------------------------------------------------------------------------
__device__ float g_X[(size_t)NROWS * KDIM];  // tf32-rounded x
__device__ float g_W[(size_t)ODIM * KDIM];   // tf32-rounded sampled weight
__device__ float g_B[ODIM];                  // sampled bias (fp32)

// ---------------------------------------------------------------------------
// Helpers (baseline sm_103 ISA: cp.async / ldmatrix / mma.sync / cvt.rna.tf32)
// ---------------------------------------------------------------------------
__device__ __forceinline__ uint32_t smem_u32(const void* p) {
    uint32_t a;
    asm("{ .reg .u64 t; cvta.to.shared.u64 t, %1; cvt.u32.u64 %0, t; }"
        : "=r"(a) : "l"(p));
    return a;
}

__device__ __forceinline__ void cp16(uint32_t smem_dst, const void* gptr) {
    asm volatile("cp.async.cg.shared.global [%0], [%1], 16;"
                 :: "r"(smem_dst), "l"(gptr) : "memory");
}
#define CP_COMMIT() asm volatile("cp.async.commit_group;" ::: "memory")
#define CP_WAIT1()  asm volatile("cp.async.wait_group 1;" ::: "memory")

__device__ __forceinline__ uint32_t f2tf32(float x) {
    uint32_t o;
    asm("cvt.rna.tf32.f32 %0, %1;" : "=r"(o) : "f"(x));
    return o;
}

// ldmatrix x4 on b16 interpreting 32-bit tf32 data: each 8x8 b16 matrix is an
// 8x4 tf32 tile; lane l receives tf32 element (row l/4, col l%4) -> exactly
// the m16n8k8 tf32 fragment layout for both A (row) and B (col) operands.
__device__ __forceinline__ void ldsm_x4(uint32_t& r0, uint32_t& r1,
                                        uint32_t& r2, uint32_t& r3,
                                        uint32_t addr) {
    asm volatile("ldmatrix.sync.aligned.m8n8.x4.shared.b16 {%0,%1,%2,%3}, [%4];"
                 : "=r"(r0), "=r"(r1), "=r"(r2), "=r"(r3) : "r"(addr));
}

__device__ __forceinline__ void mma_tf32(float* c, const uint32_t* a,
                                         uint32_t b0, uint32_t b1) {
    asm volatile(
        "mma.sync.aligned.m16n8k8.row.col.f32.tf32.tf32.f32 "
        "{%0,%1,%2,%3}, {%4,%5,%6,%7}, {%8,%9}, {%0,%1,%2,%3};"
        : "+f"(c[0]), "+f"(c[1]), "+f"(c[2]), "+f"(c[3])
        : "r"(a[0]), "r"(a[1]), "r"(a[2]), "r"(a[3]), "r"(b0), "r"(b1));
}

// ---------------------------------------------------------------------------
// Prep kernels: tf32-round X; sample + round W; sample bias
// ---------------------------------------------------------------------------
__global__ void prep_x_kernel(const float4* __restrict__ x) {
    size_t i = (size_t)blockIdx.x * blockDim.x + threadIdx.x;
    float4 v = x[i];
    float4 o;
    o.x = __uint_as_float(f2tf32(v.x));
    o.y = __uint_as_float(f2tf32(v.y));
    o.z = __uint_as_float(f2tf32(v.z));
    o.w = __uint_as_float(f2tf32(v.w));
    reinterpret_cast<float4*>(g_X)[i] = o;
}

__global__ void prep_w_kernel(const float4* __restrict__ mu,
                              const float4* __restrict__ ls,
                              const float4* __restrict__ eps) {
    size_t i = (size_t)blockIdx.x * blockDim.x + threadIdx.x;
    float4 m = mu[i], l = ls[i], e = eps[i];
    float4 o;
    o.x = __uint_as_float(f2tf32(m.x + expf(l.x) * e.x));
    o.y = __uint_as_float(f2tf32(m.y + expf(l.y) * e.y));
    o.z = __uint_as_float(f2tf32(m.z + expf(l.z) * e.z));
    o.w = __uint_as_float(f2tf32(m.w + expf(l.w) * e.w));
    reinterpret_cast<float4*>(g_W)[i] = o;
}

__global__ void prep_bias_kernel(const float* __restrict__ mub,
                                 const float* __restrict__ lsb,
                                 const float* __restrict__ epsb) {
    int i = blockIdx.x * blockDim.x + threadIdx.x;
    if (i < ODIM) g_B[i] = mub[i] + expf(lsb[i]) * epsb[i];
}

// ---------------------------------------------------------------------------
// GEMM: 2048 CTAs (64 m x 32 n tiles, n fastest => W L2-hot), 256 threads.
// 8 warps 2x4; warp tile 64x32. Fragments via ldmatrix.b16 (tf32 reinterp).
// ---------------------------------------------------------------------------
struct Producer {
    const float* gA;
    const float* gB;
    uint32_t swoff;
    uint32_t sb;
};

__device__ __forceinline__ void load_stage(const Producer& p, int slot, int kit) {
    uint32_t aB = p.sb + slot * STAGE_BYTES;
    uint32_t bB = aB + A_BYTES;
    const float* ga = p.gA + kit * TILE_K;
    const float* gb = p.gB + kit * TILE_K;
    #pragma unroll
    for (int i = 0; i < 4; ++i)
        cp16(aB + p.swoff + i * 32 * 128, ga + (size_t)i * 32 * KDIM);
    #pragma unroll
    for (int i = 0; i < 4; ++i)
        cp16(bB + p.swoff + i * 32 * 128, gb + (size_t)i * 32 * KDIM);
}

__global__ void __launch_bounds__(256, 2)
rand_linear_gemm_kernel(float* __restrict__ out) {
    extern __shared__ char smem[];
    const uint32_t sb = smem_u32(smem);
    const int tid = threadIdx.x;
    const int lane = tid & 31;
    const int wid = tid >> 5;

    const int m_tile = blockIdx.x >> 5;    // 64
    const int n_tile = blockIdx.x & 31;    // 32 (fast-varying)
    const int m0 = m_tile * TILE_M;
    const int n0 = n_tile * TILE_N;
    const int wm0 = (wid & 1) * 64;
    const int wn0 = (wid >> 1) * 32;

    // ---- producer mapping: 256 threads fill A(128x32) + B(128x32) ----
    const int tr = tid >> 3;
    const int tc = tid & 7;
    Producer p;
    p.gA = g_X + (size_t)(m0 + tr) * KDIM + tc * 4;
    p.gB = g_W + (size_t)(n0 + tr) * KDIM + tc * 4;
    p.swoff = (uint32_t)tr * 128u + (uint32_t)((tc ^ (tr & 7)) << 4);
    p.sb = sb;

    // ---- ldmatrix lane addressing ----
    // Fragment rows: lane&15 within a 16-row block; lanes>=16 take k-hi chunk.
    const int la15 = lane & 15;
    const uint32_t hi = (uint32_t)(lane >> 4);          // 0 or 1
    uint32_t aRow[4], aX7[4];
    #pragma unroll
    for (int i = 0; i < 4; ++i) {
        const uint32_t r = (uint32_t)(wm0 + i * 16 + la15);
        aRow[i] = r * 128u;
        aX7[i] = r & 7u;
    }
    uint32_t bRow[2], bX7[2];
    #pragma unroll
    for (int j2 = 0; j2 < 2; ++j2) {
        const uint32_t r = (uint32_t)(wn0 + j2 * 16 + la15);
        bRow[j2] = r * 128u;
        bX7[j2] = r & 7u;
    }

    float acc[4][4][4];
    #pragma unroll
    for (int i = 0; i < 4; ++i)
        #pragma unroll
        for (int j = 0; j < 4; ++j)
            #pragma unroll
            for (int r = 0; r < 4; ++r) acc[i][j][r] = 0.f;

    load_stage(p, 0, 0); CP_COMMIT();
    load_stage(p, 1, 1); CP_COMMIT();

    for (int it = 0; it < K_ITERS; ++it) {
        CP_WAIT1();
        __syncthreads();

        const int pf = it + 2;
        if (pf < K_ITERS) load_stage(p, pf % STAGES, pf);
        CP_COMMIT();

        const int slot = it % STAGES;
        const uint32_t aB = sb + slot * STAGE_BYTES;
        const uint32_t bB = aB + A_BYTES;

        #pragma unroll
        for (int kk = 0; kk < 4; ++kk) {
            const uint32_t kc2 = (uint32_t)(kk * 2) + hi;  // 16B chunk index
            uint32_t a[4][4];
            #pragma unroll
            for (int i = 0; i < 4; ++i)
                ldsm_x4(a[i][0], a[i][1], a[i][2], a[i][3],
                        aB + aRow[i] + ((kc2 ^ aX7[i]) << 4));
            uint32_t b[2][4];
            #pragma unroll
            for (int j2 = 0; j2 < 2; ++j2)
                ldsm_x4(b[j2][0], b[j2][1], b[j2][2], b[j2][3],
                        bB + bRow[j2] + ((kc2 ^ bX7[j2]) << 4));
            #pragma unroll
            for (int i = 0; i < 4; ++i) {
                #pragma unroll
                for (int j2 = 0; j2 < 2; ++j2) {
                    mma_tf32(acc[i][2 * j2 + 0], a[i], b[j2][0], b[j2][2]);
                    mma_tf32(acc[i][2 * j2 + 1], a[i], b[j2][1], b[j2][3]);
                }
            }
        }
    }

    // ---- epilogue: fused bias ----
    const int gid = lane >> 2;
    const int kc = lane & 3;
    #pragma unroll
    for (int j = 0; j < 4; ++j) {
        const int col = n0 + wn0 + j * 8 + kc * 2;
        float2 bv;
        bv.x = __ldg(&g_B[col]);
        bv.y = __ldg(&g_B[col + 1]);
        #pragma unroll
        for (int i = 0; i < 4; ++i) {
            const int row = m0 + wm0 + i * 16 + gid;
            float2 v0 = make_float2(acc[i][j][0] + bv.x, acc[i][j][1] + bv.y);
            float2 v1 = make_float2(acc[i][j][2] + bv.x, acc[i][j][3] + bv.y);
            *reinterpret_cast<float2*>(out + (size_t)row * ODIM + col) = v0;
            *reinterpret_cast<float2*>(out + (size_t)(row + 8) * ODIM + col) = v1;
        }
    }
}

// ---------------------------------------------------------------------------
// Launch
// ---------------------------------------------------------------------------
extern "C" void kernel_launch(void* const* d_in, const int* in_sizes, int n_in,
                              void* d_out, int out_size) {
    const float* x    = (const float*)d_in[0];
    const float* muw  = (const float*)d_in[1];
    const float* lsw  = (const float*)d_in[2];
    const float* mub  = (const float*)d_in[3];
    const float* lsb  = (const float*)d_in[4];
    const float* epsw = (const float*)d_in[5];
    const float* epsb = (const float*)d_in[6];
    float* out = (float*)d_out;

    cudaFuncSetAttribute(rand_linear_gemm_kernel,
                         cudaFuncAttributeMaxDynamicSharedMemorySize, SMEM_TOTAL);

    prep_x_kernel<<<32768, 256>>>((const float4*)x);
    prep_w_kernel<<<16384, 256>>>((const float4*)muw, (const float4*)lsw,
                                  (const float4*)epsw);
    prep_bias_kernel<<<16, 256>>>(mub, lsb, epsb);

    rand_linear_gemm_kernel<<<(NROWS / TILE_M) * (ODIM / TILE_N), 256,
                              SMEM_TOTAL>>>(out);
}

// round 4
// speedup vs baseline: 1.0580x; 1.0079x over previous
#include <cuda_runtime.h>
#include <cstdint>
#include <cstddef>

// ---------------------------------------------------------------------------
// out[8192,4096] = x[8192,4096] @ W^T + b,  W = mu + exp(log_sigma)*eps
// tf32 mma.sync path (tcgen05 rejected by harness virtual target compute_103)
// R4: warp tile 64x32 -> 64x64 (halves LDSM traffic/MAC), frag double-buffer
// ---------------------------------------------------------------------------
#define NROWS 8192
#define KDIM  4096
#define ODIM  4096

#define TILE_M 128
#define TILE_N 128
#define TILE_K 32
#define STAGES 3
#define K_ITERS (KDIM / TILE_K)            // 128

#define A_BYTES (TILE_M * TILE_K * 4)      // 16384
#define B_BYTES (TILE_N * TILE_K * 4)      // 16384
#define STAGE_BYTES (A_BYTES + B_BYTES)    // 32768
#define SMEM_TOTAL  (STAGES * STAGE_BYTES) // 98304

// ---------------------------------------------------------------------------
// Scratch (__device__ globals: sanctioned allocation-free workaround)
// ---------------------------------------------------------------------------
__device__ float g_X[(size_t)NROWS * KDIM];  // tf32-rounded x
__device__ float g_W[(size_t)ODIM * KDIM];   // tf32-rounded sampled weight
__device__ float g_B[ODIM];                  // sampled bias

// ---------------------------------------------------------------------------
// Helpers
// ---------------------------------------------------------------------------
__device__ __forceinline__ uint32_t smem_u32(const void* p) {
    uint32_t a;
    asm("{ .reg .u64 t; cvta.to.shared.u64 t, %1; cvt.u32.u64 %0, t; }"
        : "=r"(a) : "l"(p));
    return a;
}

__device__ __forceinline__ void cp16(uint32_t smem_dst, const void* gptr) {
    asm volatile("cp.async.cg.shared.global [%0], [%1], 16;"
                 :: "r"(smem_dst), "l"(gptr) : "memory");
}
#define CP_COMMIT() asm volatile("cp.async.commit_group;" ::: "memory")
#define CP_WAIT1()  asm volatile("cp.async.wait_group 1;" ::: "memory")

__device__ __forceinline__ uint32_t f2tf32(float x) {
    uint32_t o;
    asm("cvt.rna.tf32.f32 %0, %1;" : "=r"(o) : "f"(x));
    return o;
}

// ldmatrix.x4 on b16 over 32-bit tf32 data: delivers exactly the m16n8k8 tf32
// fragment layout (verified correct in R3, rel_err 2.9e-4).
__device__ __forceinline__ void ldsm_x4(uint32_t* r, uint32_t addr) {
    asm volatile("ldmatrix.sync.aligned.m8n8.x4.shared.b16 {%0,%1,%2,%3}, [%4];"
                 : "=r"(r[0]), "=r"(r[1]), "=r"(r[2]), "=r"(r[3]) : "r"(addr));
}

__device__ __forceinline__ void mma_tf32(float* c, const uint32_t* a,
                                         uint32_t b0, uint32_t b1) {
    asm volatile(
        "mma.sync.aligned.m16n8k8.row.col.f32.tf32.tf32.f32 "
        "{%0,%1,%2,%3}, {%4,%5,%6,%7}, {%8,%9}, {%0,%1,%2,%3};"
        : "+f"(c[0]), "+f"(c[1]), "+f"(c[2]), "+f"(c[3])
        : "r"(a[0]), "r"(a[1]), "r"(a[2]), "r"(a[3]), "r"(b0), "r"(b1));
}

// ---------------------------------------------------------------------------
// Prep kernels
// ---------------------------------------------------------------------------
__global__ void prep_x_kernel(const float4* __restrict__ x) {
    size_t i = (size_t)blockIdx.x * blockDim.x + threadIdx.x;
    float4 v = x[i];
    float4 o;
    o.x = __uint_as_float(f2tf32(v.x));
    o.y = __uint_as_float(f2tf32(v.y));
    o.z = __uint_as_float(f2tf32(v.z));
    o.w = __uint_as_float(f2tf32(v.w));
    reinterpret_cast<float4*>(g_X)[i] = o;
}

__global__ void prep_w_kernel(const float4* __restrict__ mu,
                              const float4* __restrict__ ls,
                              const float4* __restrict__ eps) {
    size_t i = (size_t)blockIdx.x * blockDim.x + threadIdx.x;
    float4 m = mu[i], l = ls[i], e = eps[i];
    float4 o;
    o.x = __uint_as_float(f2tf32(m.x + expf(l.x) * e.x));
    o.y = __uint_as_float(f2tf32(m.y + expf(l.y) * e.y));
    o.z = __uint_as_float(f2tf32(m.z + expf(l.z) * e.z));
    o.w = __uint_as_float(f2tf32(m.w + expf(l.w) * e.w));
    reinterpret_cast<float4*>(g_W)[i] = o;
}

__global__ void prep_bias_kernel(const float* __restrict__ mub,
                                 const float* __restrict__ lsb,
                                 const float* __restrict__ epsb) {
    int i = blockIdx.x * blockDim.x + threadIdx.x;
    if (i < ODIM) g_B[i] = mub[i] + expf(lsb[i]) * epsb[i];
}

// ---------------------------------------------------------------------------
// GEMM: 2048 CTAs (64 m x 32 n, n fastest => W L2-hot), 128 threads.
// 4 warps in 2x2; each warp computes 64x64 via m16n8k8, frags double-buffered.
// ---------------------------------------------------------------------------
__global__ void __launch_bounds__(128, 2)
rand_linear_gemm_kernel(float* __restrict__ out) {
    extern __shared__ char smem[];
    const uint32_t sb = smem_u32(smem);
    const int tid = threadIdx.x;
    const int lane = tid & 31;
    const int wid = tid >> 5;              // 0..3

    const int m_tile = blockIdx.x >> 5;    // 64
    const int n_tile = blockIdx.x & 31;    // 32 (fast-varying)
    const int m0 = m_tile * TILE_M;
    const int n0 = n_tile * TILE_N;
    const int wm0 = (wid & 1) * 64;
    const int wn0 = (wid >> 1) * 64;

    // ---- producer mapping: 128 threads fill A(128x32) + B(128x32) ----
    const int tr = tid >> 3;               // 0..15
    const int tc = tid & 7;                // 16B chunk in 128B row
    const float* gA = g_X + (size_t)(m0 + tr) * KDIM + tc * 4;
    const float* gB = g_W + (size_t)(n0 + tr) * KDIM + tc * 4;
    uint32_t off[8];
    #pragma unroll
    for (int i = 0; i < 8; ++i) {
        const uint32_t row = (uint32_t)(tr + 16 * i);
        off[i] = row * 128u + (uint32_t)((tc ^ (row & 7)) << 4);
    }

    #define LOAD_STAGE(slot, kit)                                            \
        do {                                                                  \
            const uint32_t aS = sb + (slot) * STAGE_BYTES;                    \
            const uint32_t bS = aS + A_BYTES;                                 \
            const float* ga = gA + (kit) * TILE_K;                            \
            const float* gb = gB + (kit) * TILE_K;                            \
            _Pragma("unroll")                                                 \
            for (int i_ = 0; i_ < 8; ++i_)                                    \
                cp16(aS + off[i_], ga + (size_t)i_ * 16 * KDIM);              \
            _Pragma("unroll")                                                 \
            for (int i_ = 0; i_ < 8; ++i_)                                    \
                cp16(bS + off[i_], gb + (size_t)i_ * 16 * KDIM);              \
        } while (0)

    // ---- ldmatrix lane addressing (16 rows per x4; lanes>=16 take k-hi) ----
    const int la15 = lane & 15;
    const uint32_t hi = (uint32_t)(lane >> 4);
    uint32_t aRow[4], aX7[4], bRow[4], bX7[4];
    #pragma unroll
    for (int i = 0; i < 4; ++i) {
        const uint32_t ra = (uint32_t)(wm0 + i * 16 + la15);
        aRow[i] = ra * 128u; aX7[i] = ra & 7u;
        const uint32_t rb = (uint32_t)(wn0 + i * 16 + la15);
        bRow[i] = rb * 128u; bX7[i] = rb & 7u;
    }

    float acc[4][8][4];
    #pragma unroll
    for (int i = 0; i < 4; ++i)
        #pragma unroll
        for (int j = 0; j < 8; ++j)
            #pragma unroll
            for (int r = 0; r < 4; ++r) acc[i][j][r] = 0.f;

    LOAD_STAGE(0, 0); CP_COMMIT();
    LOAD_STAGE(1, 1); CP_COMMIT();

    uint32_t a[2][4][4], b[2][4][4];

    #define LOAD_FRAGS(kk, buf, aB_, bB_)                                     \
        do {                                                                  \
            const uint32_t kc2 = (uint32_t)((kk) * 2) + hi;                   \
            _Pragma("unroll")                                                 \
            for (int i_ = 0; i_ < 4; ++i_)                                    \
                ldsm_x4(a[buf][i_], (aB_) + aRow[i_] + ((kc2 ^ aX7[i_]) << 4)); \
            _Pragma("unroll")                                                 \
            for (int j_ = 0; j_ < 4; ++j_)                                    \
                ldsm_x4(b[buf][j_], (bB_) + bRow[j_] + ((kc2 ^ bX7[j_]) << 4)); \
        } while (0)

    for (int it = 0; it < K_ITERS; ++it) {
        CP_WAIT1();
        __syncthreads();

        const int pf = it + 2;
        if (pf < K_ITERS) {
            LOAD_STAGE(pf % STAGES, pf);
        }
        CP_COMMIT();

        const int slot = it % STAGES;
        const uint32_t aB = sb + slot * STAGE_BYTES;
        const uint32_t bB = aB + A_BYTES;

        LOAD_FRAGS(0, 0, aB, bB);
        #pragma unroll
        for (int kk = 0; kk < 4; ++kk) {
            const int cur = kk & 1;
            if (kk < 3) LOAD_FRAGS(kk + 1, cur ^ 1, aB, bB);
            #pragma unroll
            for (int i = 0; i < 4; ++i) {
                #pragma unroll
                for (int j = 0; j < 4; ++j) {
                    mma_tf32(acc[i][2 * j + 0], a[cur][i], b[cur][j][0],
                             b[cur][j][2]);
                    mma_tf32(acc[i][2 * j + 1], a[cur][i], b[cur][j][1],
                             b[cur][j][3]);
                }
            }
        }
    }

    // ---- epilogue: fused bias ----
    const int gid = lane >> 2;
    const int kc = lane & 3;
    #pragma unroll
    for (int j = 0; j < 8; ++j) {
        const int col = n0 + wn0 + j * 8 + kc * 2;
        float2 bv;
        bv.x = __ldg(&g_B[col]);
        bv.y = __ldg(&g_B[col + 1]);
        #pragma unroll
        for (int i = 0; i < 4; ++i) {
            const int row = m0 + wm0 + i * 16 + gid;
            float2 v0 = make_float2(acc[i][j][0] + bv.x, acc[i][j][1] + bv.y);
            float2 v1 = make_float2(acc[i][j][2] + bv.x, acc[i][j][3] + bv.y);
            *reinterpret_cast<float2*>(out + (size_t)row * ODIM + col) = v0;
            *reinterpret_cast<float2*>(out + (size_t)(row + 8) * ODIM + col) = v1;
        }
    }
}

// ---------------------------------------------------------------------------
// Launch
// ---------------------------------------------------------------------------
extern "C" void kernel_launch(void* const* d_in, const int* in_sizes, int n_in,
                              void* d_out, int out_size) {
    const float* x    = (const float*)d_in[0];
    const float* muw  = (const float*)d_in[1];
    const float* lsw  = (const float*)d_in[2];
    const float* mub  = (const float*)d_in[3];
    const float* lsb  = (const float*)d_in[4];
    const float* epsw = (const float*)d_in[5];
    const float* epsb = (const float*)d_in[6];
    float* out = (float*)d_out;

    cudaFuncSetAttribute(rand_linear_gemm_kernel,
                         cudaFuncAttributeMaxDynamicSharedMemorySize, SMEM_TOTAL);

    prep_x_kernel<<<32768, 256>>>((const float4*)x);
    prep_w_kernel<<<16384, 256>>>((const float4*)muw, (const float4*)lsw,
                                  (const float4*)epsw);
    prep_bias_kernel<<<16, 256>>>(mub, lsb, epsb);

    rand_linear_gemm_kernel<<<(NROWS / TILE_M) * (ODIM / TILE_N), 128,
                              SMEM_TOTAL>>>(out);
}